// round 1
// baseline (speedup 1.0000x reference)
#include <cuda_runtime.h>
#include <cstdint>
#include <cstddef>

// Problem constants (fixed shapes for this problem)
#define S_MAX   4096
#define D_DIM   256
#define NH      8
#define HD      32
#define H_DIM   256
#define NEG_BIG (-3.402823466e38f)

// ---------------- device scratch (no cudaMalloc allowed) ----------------
__device__ float g_q[S_MAX * H_DIM];              // q = queries@Wq + bq
__device__ float g_qk[S_MAX * NH * D_DIM];        // qk[s][h][j]
__device__ float g_qb[S_MAX * NH];                // qb[s][h]
__device__ float g_Ahat[S_MAX * NH * D_DIM];      // A/denom
__device__ float g_pooled[S_MAX * H_DIM];
__device__ int   g_off[S_MAX + 1];

// ---------------- K0: segment offsets via binary search (idx sorted) ----
__global__ void k_offsets(const int* __restrict__ map, int N, int S) {
    int s = blockIdx.x * blockDim.x + threadIdx.x;
    if (s > S) return;
    int lo = 0, hi = N;
    while (lo < hi) {
        int mid = (lo + hi) >> 1;
        if (map[mid] < s) lo = mid + 1; else hi = mid;
    }
    g_off[s] = lo;
}

// ---------------- generic tiled GEMM: C = A[MxK] @ B[KxN] + bias --------
__global__ void __launch_bounds__(256)
k_gemm_bias(const float* __restrict__ A, const float* __restrict__ B,
            const float* __restrict__ bias, float* __restrict__ C,
            int M, int K, int N) {
    __shared__ float As[16][64];
    __shared__ float Bs[16][68];
    int t  = threadIdx.x;
    int bm = blockIdx.x * 64, bn = blockIdx.y * 64;
    int tx = t & 15, ty = t >> 4;
    float acc[4][4] = {};
    int ar = t >> 2,  ac4 = (t & 3)  * 4;
    int br = t >> 4,  bc4 = (t & 15) * 4;
    for (int k0 = 0; k0 < K; k0 += 16) {
        float4 av = *(const float4*)&A[(size_t)(bm + ar) * K + k0 + ac4];
        As[ac4 + 0][ar] = av.x; As[ac4 + 1][ar] = av.y;
        As[ac4 + 2][ar] = av.z; As[ac4 + 3][ar] = av.w;
        *(float4*)&Bs[br][bc4] = *(const float4*)&B[(size_t)(k0 + br) * N + bn + bc4];
        __syncthreads();
#pragma unroll
        for (int k = 0; k < 16; k++) {
            float ra[4], rb[4];
#pragma unroll
            for (int i = 0; i < 4; i++) ra[i] = As[k][ty * 4 + i];
#pragma unroll
            for (int j = 0; j < 4; j++) rb[j] = Bs[k][tx * 4 + j];
#pragma unroll
            for (int i = 0; i < 4; i++)
#pragma unroll
                for (int j = 0; j < 4; j++)
                    acc[i][j] += ra[i] * rb[j];
        }
        __syncthreads();
    }
#pragma unroll
    for (int i = 0; i < 4; i++) {
        int row = bm + ty * 4 + i;
#pragma unroll
        for (int j = 0; j < 4; j++) {
            int col = bn + tx * 4 + j;
            C[(size_t)row * N + col] = acc[i][j] + bias[col];
        }
    }
}

// ---------------- K2: qk[s][h][j] = sum_d q[s][h*32+d]*Wk[j][h*32+d] ----
__global__ void __launch_bounds__(256)
k_qk(const float* __restrict__ Wkv, const float* __restrict__ bkv) {
    int s0 = blockIdx.x * 32, h = blockIdx.y;
    int t = threadIdx.x;
    __shared__ float sQ[32][36];
    __shared__ float sW[256][36];
    __shared__ float sBk[32];
    {   // load q slice [32 s][32 d]
        int s = t >> 3, d4 = (t & 7) * 4;
        float4 v = *(const float4*)&g_q[(size_t)(s0 + s) * H_DIM + h * HD + d4];
        sQ[s][d4 + 0] = v.x; sQ[s][d4 + 1] = v.y;
        sQ[s][d4 + 2] = v.z; sQ[s][d4 + 3] = v.w;
    }
    if (t < 32) sBk[t] = bkv[h * HD + t];
    {   // load Wk slice [256 j][32 d], coalesced on d
        int d = t & 31;
        for (int j = t >> 5; j < 256; j += 8)
            sW[j][d] = Wkv[(size_t)j * 512 + h * HD + d];
    }
    __syncthreads();
    float wreg[32];
#pragma unroll
    for (int i = 0; i < 8; i++) {
        float4 v = *(float4*)&sW[t][i * 4];
        wreg[i * 4 + 0] = v.x; wreg[i * 4 + 1] = v.y;
        wreg[i * 4 + 2] = v.z; wreg[i * 4 + 3] = v.w;
    }
    float* outp = g_qk + (size_t)s0 * (NH * D_DIM) + h * D_DIM + t;
    for (int s = 0; s < 32; s++) {
        float acc = 0.f;
#pragma unroll
        for (int d = 0; d < 32; d++) acc += sQ[s][d] * wreg[d];
        outp[(size_t)s * (NH * D_DIM)] = acc;
    }
    if (t < 32) {
        float acc = 0.f;
#pragma unroll
        for (int d = 0; d < 32; d++) acc += sQ[t][d] * sBk[d];
        g_qb[(s0 + t) * NH + h] = acc;
    }
}

// ---------------- K3: streaming online-softmax accumulation -------------
// One block per sample. Computes A[h][j] = sum_n p[n,h]*emb[n,j] with
// running max/denominator, writes Ahat = A/denom.
__global__ void __launch_bounds__(256)
k_attn(const float* __restrict__ emb, float scale) {
    int s = blockIdx.x;
    int t = threadIdx.x;
    int lane = t & 31, w = t >> 5;

    __shared__ float sQK[NH][260];
    __shared__ float sE[32][260];
    __shared__ float sP[32][12];
    __shared__ float sF[NH];
    __shared__ float sD[NH];
    __shared__ float sQBs[NH];

    const float* qkp = g_qk + (size_t)s * (NH * D_DIM);
    for (int i = t; i < (NH * D_DIM) / 4; i += 256) {
        float4 v = *(const float4*)(qkp + i * 4);
        int h = i >> 6, j = (i * 4) & 255;
        *(float4*)&sQK[h][j] = v;
    }
    if (t < NH) sQBs[t] = g_qb[s * NH + t];

    int start = g_off[s], end = g_off[s + 1];
    float a[NH];
#pragma unroll
    for (int i = 0; i < NH; i++) a[i] = 0.f;
    float m_w = NEG_BIG, d_w = 0.f;
    __syncthreads();

    for (int t0 = start; t0 < end; t0 += 32) {
        int T = min(32, end - t0);
        // load embedding tile (coalesced float4)
        for (int i = t; i < T * 64; i += 256) {
            int e = i >> 6, j4 = (i & 63) * 4;
            *(float4*)&sE[e][j4] = *(const float4*)(emb + (size_t)(t0 + e) * D_DIM + j4);
        }
        __syncthreads();

        // scores: thread (e=lane, h=w)
        float sc = NEG_BIG, p = 0.f;
        if (lane < T) {
            float acc = 0.f;
#pragma unroll
            for (int j4 = 0; j4 < 64; j4++) {
                float4 ev = *(float4*)&sE[lane][j4 * 4];
                float4 qv = *(float4*)&sQK[w][j4 * 4];
                acc += ev.x * qv.x + ev.y * qv.y + ev.z * qv.z + ev.w * qv.w;
            }
            sc = scale * (acc + sQBs[w]);
        }
        float mt = sc;
#pragma unroll
        for (int o = 16; o; o >>= 1) mt = fmaxf(mt, __shfl_xor_sync(0xffffffffu, mt, o));
        float mnew = fmaxf(m_w, mt);
        float factor = __expf(m_w - mnew);
        if (lane < T) p = __expf(sc - mnew);
        sP[lane][w] = p;
        float ps = p;
#pragma unroll
        for (int o = 16; o; o >>= 1) ps += __shfl_xor_sync(0xffffffffu, ps, o);
        d_w = d_w * factor + ps;
        m_w = mnew;
        if (lane == 0) sF[w] = factor;
        __syncthreads();

        // A update: thread owns column j = t for all 8 heads
#pragma unroll
        for (int h = 0; h < NH; h++) a[h] *= sF[h];
        for (int e = 0; e < T; e++) {
            float4 p0 = *(float4*)&sP[e][0];
            float4 p1 = *(float4*)&sP[e][4];
            float ev = sE[e][t];
            a[0] += p0.x * ev; a[1] += p0.y * ev; a[2] += p0.z * ev; a[3] += p0.w * ev;
            a[4] += p1.x * ev; a[5] += p1.y * ev; a[6] += p1.z * ev; a[7] += p1.w * ev;
        }
        __syncthreads();
    }

    if (lane == 0) sD[w] = d_w;
    __syncthreads();
    float* outp = g_Ahat + (size_t)s * (NH * D_DIM);
#pragma unroll
    for (int h = 0; h < NH; h++) {
        float dh = sD[h];
        outp[h * D_DIM + t] = (dh > 0.f) ? (a[h] / dh) : 0.f;
    }
}

// ---------------- K4: pooled = Ahat @ Wv (+ bv if nonempty) -------------
__global__ void __launch_bounds__(256)
k_pool(const float* __restrict__ Wkv, const float* __restrict__ bkv) {
    int s0 = blockIdx.x * 32, h = blockIdx.y;
    int t = threadIdx.x;
    __shared__ float sA[32][132];
    __shared__ float sWt[32][132];   // sWt[d][j] = Wv[j][h*32+d]
    float acc[4] = {0.f, 0.f, 0.f, 0.f};
    int d = t & 31, sl0 = (t >> 5) * 4;

    for (int jc = 0; jc < 2; jc++) {
        for (int i = t; i < 32 * 32; i += 256) {
            int r = i >> 5, j4 = (i & 31) * 4;
            *(float4*)&sA[r][j4] =
                *(const float4*)&g_Ahat[(size_t)(s0 + r) * (NH * D_DIM) + h * D_DIM + jc * 128 + j4];
        }
        {
            int dd = t & 31;
            for (int j = t >> 5; j < 128; j += 8)
                sWt[dd][j] = Wkv[(size_t)(jc * 128 + j) * 512 + 256 + h * HD + dd];
        }
        __syncthreads();
#pragma unroll
        for (int j4 = 0; j4 < 32; j4++) {
            float4 wv = *(float4*)&sWt[d][j4 * 4];
#pragma unroll
            for (int q = 0; q < 4; q++) {
                float4 av = *(float4*)&sA[sl0 + q][j4 * 4];
                acc[q] += av.x * wv.x + av.y * wv.y + av.z * wv.z + av.w * wv.w;
            }
        }
        __syncthreads();
    }
    float bv = bkv[256 + h * HD + d];
#pragma unroll
    for (int q = 0; q < 4; q++) {
        int srow = s0 + sl0 + q;
        float ne = (g_off[srow + 1] > g_off[srow]) ? bv : 0.f;
        g_pooled[(size_t)srow * H_DIM + h * HD + d] = acc[q] + ne;
    }
}

// ---------------- launch ----------------
extern "C" void kernel_launch(void* const* d_in, const int* in_sizes, int n_in,
                              void* d_out, int out_size) {
    const float* queries = (const float*)d_in[0];
    const float* emb     = (const float*)d_in[1];
    const int*   map     = (const int*)  d_in[2];
    // num_samples may or may not be materialized as a device input
    int base = (n_in >= 10 && in_sizes[3] < 16) ? 4 : 3;
    const float* Wq  = (const float*)d_in[base + 0];
    const float* bq  = (const float*)d_in[base + 1];
    const float* Wkv = (const float*)d_in[base + 2];
    const float* bkv = (const float*)d_in[base + 3];
    const float* Wo  = (const float*)d_in[base + 4];
    const float* bo  = (const float*)d_in[base + 5];
    float* out = (float*)d_out;

    int S = in_sizes[0] / D_DIM;     // 4096
    int N = in_sizes[1] / D_DIM;     // 262144
    float scale = 0.17677669529663687f;   // 1/sqrt(32)

    float* dq      = nullptr; cudaGetSymbolAddress((void**)&dq,      g_q);
    float* dpooled = nullptr; cudaGetSymbolAddress((void**)&dpooled, g_pooled);

    // K0: segment offsets
    k_offsets<<<(S + 1 + 255) / 256, 256>>>(map, N, S);
    // K1: q projection
    {
        dim3 grid(S / 64, H_DIM / 64);
        k_gemm_bias<<<grid, 256>>>(queries, Wq, bq, dq, S, D_DIM, H_DIM);
    }
    // K2: qk/qb precompute
    {
        dim3 grid(S / 32, NH);
        k_qk<<<grid, 256>>>(Wkv, bkv);
    }
    // K3: streaming attention accumulation
    k_attn<<<S, 256>>>(emb, scale);
    // K4: pooled projection through Wv
    {
        dim3 grid(S / 32, NH);
        k_pool<<<grid, 256>>>(Wkv, bkv);
    }
    // K5: output projection
    {
        dim3 grid(S / 64, H_DIM / 64);
        k_gemm_bias<<<grid, 256>>>(dpooled, Wo, bo, out, S, H_DIM, H_DIM);
    }
}

// round 2
// speedup vs baseline: 1.1909x; 1.1909x over previous
#include <cuda_runtime.h>
#include <cstdint>
#include <cstddef>

// Problem constants (fixed shapes for this problem)
#define S_MAX   4096
#define D_DIM   256
#define NH      8
#define HD      32
#define H_DIM   256
#define NEG_BIG (-3.402823466e38f)

// ---------------- device scratch (no cudaMalloc allowed) ----------------
__device__ float g_q[S_MAX * H_DIM];              // q = queries@Wq + bq
__device__ float g_qk[S_MAX * NH * D_DIM];        // qk[s][h][j]
__device__ float g_qb[S_MAX * NH];                // qb[s][h]
__device__ float g_Ahat[S_MAX * NH * D_DIM];      // A/denom
__device__ float g_pooled[S_MAX * H_DIM];
__device__ int   g_off[S_MAX + 1];

// ---------------- K0: segment offsets via binary search (idx sorted) ----
__global__ void k_offsets(const int* __restrict__ map, int N, int S) {
    int s = blockIdx.x * blockDim.x + threadIdx.x;
    if (s > S) return;
    int lo = 0, hi = N;
    while (lo < hi) {
        int mid = (lo + hi) >> 1;
        if (map[mid] < s) lo = mid + 1; else hi = mid;
    }
    g_off[s] = lo;
}

// ---------------- generic tiled GEMM: C = A[MxK] @ B[KxN] + bias --------
__global__ void __launch_bounds__(256)
k_gemm_bias(const float* __restrict__ A, const float* __restrict__ B,
            const float* __restrict__ bias, float* __restrict__ C,
            int M, int K, int N) {
    __shared__ float As[16][64];
    __shared__ float Bs[16][68];
    int t  = threadIdx.x;
    int bm = blockIdx.x * 64, bn = blockIdx.y * 64;
    int tx = t & 15, ty = t >> 4;
    float acc[4][4] = {};
    int ar = t >> 2,  ac4 = (t & 3)  * 4;
    int br = t >> 4,  bc4 = (t & 15) * 4;
    for (int k0 = 0; k0 < K; k0 += 16) {
        float4 av = *(const float4*)&A[(size_t)(bm + ar) * K + k0 + ac4];
        As[ac4 + 0][ar] = av.x; As[ac4 + 1][ar] = av.y;
        As[ac4 + 2][ar] = av.z; As[ac4 + 3][ar] = av.w;
        *(float4*)&Bs[br][bc4] = *(const float4*)&B[(size_t)(k0 + br) * N + bn + bc4];
        __syncthreads();
#pragma unroll
        for (int k = 0; k < 16; k++) {
            float ra[4], rb[4];
#pragma unroll
            for (int i = 0; i < 4; i++) ra[i] = As[k][ty * 4 + i];
#pragma unroll
            for (int j = 0; j < 4; j++) rb[j] = Bs[k][tx * 4 + j];
#pragma unroll
            for (int i = 0; i < 4; i++)
#pragma unroll
                for (int j = 0; j < 4; j++)
                    acc[i][j] += ra[i] * rb[j];
        }
        __syncthreads();
    }
#pragma unroll
    for (int i = 0; i < 4; i++) {
        int row = bm + ty * 4 + i;
#pragma unroll
        for (int j = 0; j < 4; j++) {
            int col = bn + tx * 4 + j;
            C[(size_t)row * N + col] = acc[i][j] + bias[col];
        }
    }
}

// ---------------- K2: qk[s][h][j] = sum_d q[s][h*32+d]*Wk[j][h*32+d] ----
__global__ void __launch_bounds__(256)
k_qk(const float* __restrict__ Wkv, const float* __restrict__ bkv) {
    int s0 = blockIdx.x * 32, h = blockIdx.y;
    int t = threadIdx.x;
    __shared__ float sQ[32][36];
    __shared__ float sW[256][36];
    __shared__ float sBk[32];
    {   // load q slice [32 s][32 d]
        int s = t >> 3, d4 = (t & 7) * 4;
        float4 v = *(const float4*)&g_q[(size_t)(s0 + s) * H_DIM + h * HD + d4];
        sQ[s][d4 + 0] = v.x; sQ[s][d4 + 1] = v.y;
        sQ[s][d4 + 2] = v.z; sQ[s][d4 + 3] = v.w;
    }
    if (t < 32) sBk[t] = bkv[h * HD + t];
    {   // load Wk slice [256 j][32 d], coalesced on d
        int d = t & 31;
        for (int j = t >> 5; j < 256; j += 8)
            sW[j][d] = Wkv[(size_t)j * 512 + h * HD + d];
    }
    __syncthreads();
    float wreg[32];
#pragma unroll
    for (int i = 0; i < 8; i++) {
        float4 v = *(float4*)&sW[t][i * 4];
        wreg[i * 4 + 0] = v.x; wreg[i * 4 + 1] = v.y;
        wreg[i * 4 + 2] = v.z; wreg[i * 4 + 3] = v.w;
    }
    float* outp = g_qk + (size_t)s0 * (NH * D_DIM) + h * D_DIM + t;
    for (int s = 0; s < 32; s++) {
        float acc = 0.f;
#pragma unroll
        for (int d = 0; d < 32; d++) acc += sQ[s][d] * wreg[d];
        outp[(size_t)s * (NH * D_DIM)] = acc;
    }
    if (t < 32) {
        float acc = 0.f;
#pragma unroll
        for (int d = 0; d < 32; d++) acc += sQ[t][d] * sBk[d];
        g_qb[(s0 + t) * NH + h] = acc;
    }
}

// ---------------- K3: streaming online-softmax accumulation -------------
// One block per sample. Score phase splits the 256-dim j axis across the 8
// warps so the E tile is read from smem ONCE (not once per head-warp).
// Partial scores are staged through a pad-65 smem transpose, then the
// (lane=e, warp=h) layout runs the same online-softmax shuffle code.
__global__ void __launch_bounds__(256)
k_attn(const float* __restrict__ emb, float scale) {
    int s = blockIdx.x;
    int t = threadIdx.x;
    int lane = t & 31, w = t >> 5;

    __shared__ float sQK[NH][260];
    __shared__ float sE[32][260];
    __shared__ float sPart[32 * 65 + 16];   // [e*65 + h*8 + w]
    __shared__ float sP[32][12];
    __shared__ float sF[NH];
    __shared__ float sD[NH];
    __shared__ float sQBs[NH];

    const float* qkp = g_qk + (size_t)s * (NH * D_DIM);
    for (int i = t; i < (NH * D_DIM) / 4; i += 256) {
        float4 v = *(const float4*)(qkp + i * 4);
        int h = i >> 6, j = (i * 4) & 255;
        *(float4*)&sQK[h][j] = v;
    }
    if (t < NH) sQBs[t] = g_qb[s * NH + t];

    int start = g_off[s], end = g_off[s + 1];
    float a[NH];
#pragma unroll
    for (int i = 0; i < NH; i++) a[i] = 0.f;
    float m_w = NEG_BIG, d_w = 0.f;
    int j0 = w * 32;
    __syncthreads();

    for (int t0 = start; t0 < end; t0 += 32) {
        int T = min(32, end - t0);
        // load embedding tile (coalesced float4)
        for (int i = t; i < T * 64; i += 256) {
            int e = i >> 6, j4 = (i & 63) * 4;
            *(float4*)&sE[e][j4] = *(const float4*)(emb + (size_t)(t0 + e) * D_DIM + j4);
        }
        __syncthreads();

        // ---- score partials: warp w covers j in [j0, j0+32), lane = element
        {
            float acc[NH];
#pragma unroll
            for (int h = 0; h < NH; h++) acc[h] = 0.f;
#pragma unroll
            for (int half = 0; half < 2; half++) {
                float4 er[4];
#pragma unroll
                for (int q = 0; q < 4; q++)
                    er[q] = *(float4*)&sE[lane][j0 + half * 16 + q * 4];
#pragma unroll
                for (int h = 0; h < NH; h++) {
#pragma unroll
                    for (int q = 0; q < 4; q++) {
                        float4 qv = *(float4*)&sQK[h][j0 + half * 16 + q * 4];
                        acc[h] += er[q].x * qv.x + er[q].y * qv.y
                                + er[q].z * qv.z + er[q].w * qv.w;
                    }
                }
            }
#pragma unroll
            for (int h = 0; h < NH; h++)
                sPart[lane * 65 + h * 8 + w] = acc[h];
        }
        __syncthreads();

        // ---- reduce partials: thread (lane=e, w=h)
        float sc = NEG_BIG, p = 0.f;
        if (lane < T) {
            float sum = 0.f;
#pragma unroll
            for (int i = 0; i < 8; i++) sum += sPart[lane * 65 + w * 8 + i];
            sc = scale * (sum + sQBs[w]);
        }
        float mt = sc;
#pragma unroll
        for (int o = 16; o; o >>= 1) mt = fmaxf(mt, __shfl_xor_sync(0xffffffffu, mt, o));
        float mnew = fmaxf(m_w, mt);
        float factor = __expf(m_w - mnew);
        if (lane < T) p = __expf(sc - mnew);
        sP[lane][w] = p;
        float ps = p;
#pragma unroll
        for (int o = 16; o; o >>= 1) ps += __shfl_xor_sync(0xffffffffu, ps, o);
        d_w = d_w * factor + ps;
        m_w = mnew;
        if (lane == 0) sF[w] = factor;
        __syncthreads();

        // ---- A update: thread owns column j = t for all 8 heads
#pragma unroll
        for (int h = 0; h < NH; h++) a[h] *= sF[h];
        for (int e = 0; e < T; e++) {
            float4 p0 = *(float4*)&sP[e][0];
            float4 p1 = *(float4*)&sP[e][4];
            float ev = sE[e][t];
            a[0] += p0.x * ev; a[1] += p0.y * ev; a[2] += p0.z * ev; a[3] += p0.w * ev;
            a[4] += p1.x * ev; a[5] += p1.y * ev; a[6] += p1.z * ev; a[7] += p1.w * ev;
        }
        __syncthreads();
    }

    if (lane == 0) sD[w] = d_w;
    __syncthreads();
    float* outp = g_Ahat + (size_t)s * (NH * D_DIM);
#pragma unroll
    for (int h = 0; h < NH; h++) {
        float dh = sD[h];
        outp[h * D_DIM + t] = (dh > 0.f) ? (a[h] / dh) : 0.f;
    }
}

// ---------------- K4: pooled = Ahat @ Wv (+ bv if nonempty) -------------
__global__ void __launch_bounds__(256)
k_pool(const float* __restrict__ Wkv, const float* __restrict__ bkv) {
    int s0 = blockIdx.x * 32, h = blockIdx.y;
    int t = threadIdx.x;
    __shared__ float sA[32][132];
    __shared__ float sWt[32][132];   // sWt[d][j] = Wv[j][h*32+d]
    float acc[4] = {0.f, 0.f, 0.f, 0.f};
    int d = t & 31, sl0 = (t >> 5) * 4;

    for (int jc = 0; jc < 2; jc++) {
        for (int i = t; i < 32 * 32; i += 256) {
            int r = i >> 5, j4 = (i & 31) * 4;
            *(float4*)&sA[r][j4] =
                *(const float4*)&g_Ahat[(size_t)(s0 + r) * (NH * D_DIM) + h * D_DIM + jc * 128 + j4];
        }
        {
            int dd = t & 31;
            for (int j = t >> 5; j < 128; j += 8)
                sWt[dd][j] = Wkv[(size_t)(jc * 128 + j) * 512 + 256 + h * HD + dd];
        }
        __syncthreads();
#pragma unroll
        for (int j4 = 0; j4 < 32; j4++) {
            float4 wv = *(float4*)&sWt[d][j4 * 4];
#pragma unroll
            for (int q = 0; q < 4; q++) {
                float4 av = *(float4*)&sA[sl0 + q][j4 * 4];
                acc[q] += av.x * wv.x + av.y * wv.y + av.z * wv.z + av.w * wv.w;
            }
        }
        __syncthreads();
    }
    float bv = bkv[256 + h * HD + d];
#pragma unroll
    for (int q = 0; q < 4; q++) {
        int srow = s0 + sl0 + q;
        float ne = (g_off[srow + 1] > g_off[srow]) ? bv : 0.f;
        g_pooled[(size_t)srow * H_DIM + h * HD + d] = acc[q] + ne;
    }
}

// ---------------- launch ----------------
extern "C" void kernel_launch(void* const* d_in, const int* in_sizes, int n_in,
                              void* d_out, int out_size) {
    const float* queries = (const float*)d_in[0];
    const float* emb     = (const float*)d_in[1];
    const int*   map     = (const int*)  d_in[2];
    // num_samples may or may not be materialized as a device input
    int base = (n_in >= 10 && in_sizes[3] < 16) ? 4 : 3;
    const float* Wq  = (const float*)d_in[base + 0];
    const float* bq  = (const float*)d_in[base + 1];
    const float* Wkv = (const float*)d_in[base + 2];
    const float* bkv = (const float*)d_in[base + 3];
    const float* Wo  = (const float*)d_in[base + 4];
    const float* bo  = (const float*)d_in[base + 5];
    float* out = (float*)d_out;

    int S = in_sizes[0] / D_DIM;     // 4096
    int N = in_sizes[1] / D_DIM;     // 262144
    float scale = 0.17677669529663687f;   // 1/sqrt(32)

    float* dq      = nullptr; cudaGetSymbolAddress((void**)&dq,      g_q);
    float* dpooled = nullptr; cudaGetSymbolAddress((void**)&dpooled, g_pooled);

    // K0: segment offsets
    k_offsets<<<(S + 1 + 255) / 256, 256>>>(map, N, S);
    // K1: q projection
    {
        dim3 grid(S / 64, H_DIM / 64);
        k_gemm_bias<<<grid, 256>>>(queries, Wq, bq, dq, S, D_DIM, H_DIM);
    }
    // K2: qk/qb precompute
    {
        dim3 grid(S / 32, NH);
        k_qk<<<grid, 256>>>(Wkv, bkv);
    }
    // K3: streaming attention accumulation
    k_attn<<<S, 256>>>(emb, scale);
    // K4: pooled projection through Wv
    {
        dim3 grid(S / 32, NH);
        k_pool<<<grid, 256>>>(Wkv, bkv);
    }
    // K5: output projection
    {
        dim3 grid(S / 64, H_DIM / 64);
        k_gemm_bias<<<grid, 256>>>(dpooled, Wo, bo, out, S, H_DIM, H_DIM);
    }
}